// round 6
// baseline (speedup 1.0000x reference)
#include <cuda_runtime.h>
#include <cuda_bf16.h>
#include <stdint.h>

// Scatter-mean via counting-sort + gather, 5-launch pipeline:
//   detect -> hist -> scan(one-pass decoupled lookback) -> build_perm -> gather
// gather also: normalizes, writes iota ids, zeroes g_count and scan flags for
// the next graph replay (deterministic: BSS starts zeroed).
// Fallback to a direct-atomic path for shapes exceeding static scratch.

#define MAX_NODES (1 << 20)
#define PERM_CAP  (1 << 21)
#define SCAN2_TILE 2048
#define MAX_SCAN2 128

__device__ int g_is64;
__device__ int g_count[MAX_NODES];
__device__ int g_start[MAX_NODES];
__device__ int g_cursor[MAX_NODES];
__device__ int g_perm[PERM_CAP];
__device__ int g_bsum[MAX_SCAN2];
__device__ int g_sflag[MAX_SCAN2];
__device__ float g_fcounts[MAX_NODES];   // fallback path only

// ---------- dtype detect ----------
__global__ void detect_kernel(const unsigned int* __restrict__ words, int M) {
    __shared__ int any_nonzero;
    if (threadIdx.x == 0) any_nonzero = 0;
    __syncthreads();
    int n = (M / 2) < 4096 ? (M / 2) : 4096;
    for (int i = threadIdx.x; i < n; i += blockDim.x)
        if (words[2 * i + 1] != 0u) any_nonzero = 1;   // int64 high word
    __syncthreads();
    if (threadIdx.x == 0) g_is64 = any_nonzero ? 0 : 1;
}

__device__ __forceinline__ int load_id(const void* ids, int i, bool is64) {
    return is64 ? (int)((const long long*)ids)[i] : ((const int*)ids)[i];
}

// ---------- histogram ----------
__global__ void hist_kernel(const void* __restrict__ ids, int M) {
    bool is64 = g_is64;
    int i = blockIdx.x * blockDim.x + threadIdx.x;
    int stride = gridDim.x * blockDim.x;
    for (; i < M; i += stride)
        atomicAdd(&g_count[load_id(ids, i, is64)], 1);
}

// ---------- one-pass scan with decoupled lookback ----------
// grid = ceil(N / SCAN2_TILE) blocks (<= MAX_SCAN2 <= resident capacity),
// block = 1024 threads, 2 elements per thread.
__global__ void scan_onepass(int N) {
    __shared__ int wsum[32];
    __shared__ int s_off;
    int b = blockIdx.x, tid = threadIdx.x;
    int lane = tid & 31, warp = tid >> 5;

    int base = b * SCAN2_TILE + tid * 2;
    int v0 = (base     < N) ? g_count[base]     : 0;
    int v1 = (base + 1 < N) ? g_count[base + 1] : 0;
    int s = v0 + v1;

    int x = s;
    #pragma unroll
    for (int o = 1; o < 32; o <<= 1) {
        int y = __shfl_up_sync(0xffffffffu, x, o);
        if (lane >= o) x += y;
    }
    if (lane == 31) wsum[warp] = x;
    __syncthreads();
    if (warp == 0) {
        int w = wsum[lane];
        #pragma unroll
        for (int o = 1; o < 32; o <<= 1) {
            int y = __shfl_up_sync(0xffffffffu, w, o);
            if (lane >= o) w += y;
        }
        wsum[lane] = w;
    }
    __syncthreads();
    int incl = x + (warp > 0 ? wsum[warp - 1] : 0);   // inclusive prefix of s
    int total = wsum[31];

    if (tid == 0) {
        g_bsum[b] = total;
        __threadfence();
        atomicExch(&g_sflag[b], 1);
        int off = 0;
        for (int p = 0; p < b; p++) {
            while (atomicAdd(&g_sflag[p], 0) == 0) { }
            off += atomicAdd(&g_bsum[p], 0);
        }
        s_off = off;
    }
    __syncthreads();

    int excl = incl - s + s_off;
    if (base < N)     { g_start[base]     = excl;      g_cursor[base]     = excl; }
    if (base + 1 < N) { g_start[base + 1] = excl + v0; g_cursor[base + 1] = excl + v0; }
}

// ---------- permutation ----------
__global__ void build_perm_kernel(const void* __restrict__ ids, int M) {
    bool is64 = g_is64;
    int i = blockIdx.x * blockDim.x + threadIdx.x;
    int stride = gridDim.x * blockDim.x;
    for (; i < M; i += stride) {
        int id = load_id(ids, i, is64);
        int pos = atomicAdd(&g_cursor[id], 1);
        g_perm[pos] = i;
    }
}

// ---------- gather + normalize + iota + state cleanup ----------
// One warp per node; D == 128 (32 float4 per row, 1 per lane), 2-deep pipeline.
__global__ void gather_kernel(const float4* __restrict__ msgs4,
                              float* __restrict__ out,
                              float* __restrict__ ids_out,
                              int N, int has_ids) {
    int t    = blockIdx.x * blockDim.x + threadIdx.x;
    int gw   = t >> 5;
    int lane = threadIdx.x & 31;
    if (t < MAX_SCAN2) g_sflag[t] = 0;   // reset scan flags for next replay
    if (gw >= N) return;

    int cnt   = g_count[gw];
    int start = g_start[gw];
    float4 acc = make_float4(0.f, 0.f, 0.f, 0.f);

    if (cnt > 0) {
        int idx  = g_perm[start];
        int idxn = (cnt > 1) ? g_perm[start + 1] : 0;
        float4 v = __ldg(&msgs4[(size_t)idx * 32 + lane]);
        for (int j = 1; j < cnt; j++) {
            int idxn2 = (j + 1 < cnt) ? g_perm[start + j + 1] : 0;
            float4 v2 = __ldg(&msgs4[(size_t)idxn * 32 + lane]);
            acc.x += v.x; acc.y += v.y; acc.z += v.z; acc.w += v.w;
            v = v2; idxn = idxn2;
        }
        acc.x += v.x; acc.y += v.y; acc.z += v.z; acc.w += v.w;
    }

    float inv = (cnt > 0) ? (1.0f / (float)cnt) : 0.0f;
    acc.x *= inv; acc.y *= inv; acc.z *= inv; acc.w *= inv;
    ((float4*)out)[(size_t)gw * 32 + lane] = acc;

    if (lane == 0) g_count[gw] = 0;                       // re-zero for next replay
    if (lane == 1 && has_ids) ids_out[gw] = (float)gw;    // iota ids output
}

// ---------- fallback path (generic D / oversized shapes) ----------
__device__ __forceinline__ void red_add_v4(float* addr, float4 v) {
    asm volatile("red.global.add.v4.f32 [%0], {%1, %2, %3, %4};"
                 :: "l"(addr), "f"(v.x), "f"(v.y), "f"(v.z), "f"(v.w) : "memory");
}
__device__ __forceinline__ void red_add_f32(float* addr, float v) {
    asm volatile("red.global.add.f32 [%0], %1;"
                 :: "l"(addr), "f"(v) : "memory");
}

__global__ void fb_init_kernel(float* __restrict__ sums, float* __restrict__ ids_out,
                               int N, int D, int has_ids) {
    long long total = (long long)N * D;
    for (long long i = blockIdx.x * (long long)blockDim.x + threadIdx.x;
         i < total; i += (long long)gridDim.x * blockDim.x)
        sums[i] = 0.f;
    for (long long i = blockIdx.x * (long long)blockDim.x + threadIdx.x;
         i < N; i += (long long)gridDim.x * blockDim.x) {
        if (i < MAX_NODES) g_fcounts[i] = 0.f;
        if (has_ids) ids_out[i] = (float)i;
    }
}

__global__ void fb_scatter_kernel(const void* __restrict__ ids,
                                  const float* __restrict__ msgs,
                                  float* __restrict__ sums, int M, int D) {
    int gwarp = (blockIdx.x * blockDim.x + threadIdx.x) >> 5;
    int lane  = threadIdx.x & 31;
    if (gwarp >= M) return;
    int id = load_id(ids, gwarp, g_is64 != 0);
    const float* row = msgs + (size_t)gwarp * D;
    float* dst = sums + (size_t)id * D;
    for (int c = lane * 4; c + 3 < D; c += 128)
        red_add_v4(dst + c, *(const float4*)(row + c));
    for (int c = (D / 4) * 4 + lane; c < D; c += 32)
        red_add_f32(dst + c, row[c]);
    if (lane == 0) red_add_f32(&g_fcounts[id], 1.0f);
}

__global__ void fb_normalize_kernel(float* __restrict__ sums, int N, int D) {
    long long total = (long long)N * D;
    for (long long i = blockIdx.x * (long long)blockDim.x + threadIdx.x;
         i < total; i += (long long)gridDim.x * blockDim.x) {
        int row = (int)(i / D);
        float inv = 1.0f / fmaxf(g_fcounts[row], 1.0f);
        sums[i] *= inv;
    }
}

extern "C" void kernel_launch(void* const* d_in, const int* in_sizes, int n_in,
                              void* d_out, int out_size) {
    const void*  ids  = d_in[0];
    const float* msgs = (const float*)d_in[1];

    int M = in_sizes[0];
    int D = in_sizes[1] / M;   // 128

    int N, has_ids;
    if (out_size % (D + 1) == 0) { N = out_size / (D + 1); has_ids = 1; }
    else                          { N = out_size / D;       has_ids = 0; }

    float* out     = (float*)d_out;
    float* ids_out = out;
    float* sums    = has_ids ? (out + N) : out;

    detect_kernel<<<1, 256>>>((const unsigned int*)ids, M);

    int nb2 = (N + SCAN2_TILE - 1) / SCAN2_TILE;
    bool fast = (D == 128) && (N <= MAX_NODES) && (M <= PERM_CAP) && (nb2 <= MAX_SCAN2);

    if (fast) {
        {
            int blocks = (M + 255) / 256; if (blocks > 2048) blocks = 2048;
            hist_kernel<<<blocks, 256>>>(ids, M);
        }
        scan_onepass<<<nb2, 1024>>>(N);
        {
            int blocks = (M + 255) / 256; if (blocks > 2048) blocks = 2048;
            build_perm_kernel<<<blocks, 256>>>(ids, M);
        }
        {
            long long threads = (long long)N * 32;
            int blocks = (int)((threads + 255) / 256);
            gather_kernel<<<blocks, 256>>>((const float4*)msgs, sums, ids_out, N, has_ids);
        }
    } else {
        {
            long long total = (long long)N * D;
            int blocks = (int)((total + 255) / 256); if (blocks > 4096) blocks = 4096;
            fb_init_kernel<<<blocks, 256>>>(sums, ids_out, N, D, has_ids);
        }
        {
            long long threads = (long long)M * 32;
            int blocks = (int)((threads + 255) / 256);
            fb_scatter_kernel<<<blocks, 256>>>(ids, msgs, sums, M, D);
        }
        {
            long long total = (long long)N * D;
            int blocks = (int)((total + 255) / 256); if (blocks > 4096) blocks = 4096;
            fb_normalize_kernel<<<blocks, 256>>>(sums, N, D);
        }
    }
}

// round 7
// speedup vs baseline: 1.0868x; 1.0868x over previous
#include <cuda_runtime.h>
#include <cuda_bf16.h>
#include <stdint.h>

// Scatter-mean via counting-sort + gather (no atomics in the hot loop).
// Pipeline: detect id dtype -> init -> histogram(x4) -> 3-stage parallel scan ->
//           build permutation(x4) -> gather+normalize (2-deep pipeline).
// Fallback to a direct-atomic path for shapes exceeding static scratch.

#define MAX_NODES (1 << 20)
#define PERM_CAP  (1 << 21)
#define SCAN_TILE 4096
#define MAX_SCAN_BLOCKS ((MAX_NODES + SCAN_TILE - 1) / SCAN_TILE)

__device__ int g_is64;
__device__ int g_count[MAX_NODES];
__device__ int g_start[MAX_NODES];
__device__ int g_cursor[MAX_NODES];
__device__ int g_perm[PERM_CAP];
__device__ int g_bsum[MAX_SCAN_BLOCKS];
__device__ int g_boff[MAX_SCAN_BLOCKS];
__device__ float g_fcounts[MAX_NODES];   // fallback path only

// ---------- dtype detect ----------
__global__ void detect_kernel(const unsigned int* __restrict__ words, int M) {
    __shared__ int any_nonzero;
    if (threadIdx.x == 0) any_nonzero = 0;
    __syncthreads();
    int n = (M / 2) < 4096 ? (M / 2) : 4096;
    for (int i = threadIdx.x; i < n; i += blockDim.x)
        if (words[2 * i + 1] != 0u) any_nonzero = 1;   // int64 high word
    __syncthreads();
    if (threadIdx.x == 0) g_is64 = any_nonzero ? 0 : 1;
}

__device__ __forceinline__ int load_id(const void* ids, int i, bool is64) {
    return is64 ? (int)((const long long*)ids)[i] : ((const int*)ids)[i];
}

// ---------- fast path ----------
__global__ void init_kernel(float* __restrict__ ids_out, int N, int has_ids) {
    int i = blockIdx.x * blockDim.x + threadIdx.x;
    int stride = gridDim.x * blockDim.x;
    for (; i < N; i += stride) {
        g_count[i] = 0;
        if (has_ids) ids_out[i] = (float)i;
    }
}

// Histogram: 4 independent RED ops in flight per thread-iteration.
__global__ void hist_kernel(const void* __restrict__ ids, int M) {
    bool is64 = g_is64;
    int t = blockIdx.x * blockDim.x + threadIdx.x;
    int stride = gridDim.x * blockDim.x;
    int M4 = M >> 2;
    if (is64) {
        const longlong2* p = (const longlong2*)ids;
        for (int i = t; i < M4; i += stride) {
            longlong2 a = p[2 * i], b = p[2 * i + 1];
            atomicAdd(&g_count[(int)a.x], 1);
            atomicAdd(&g_count[(int)a.y], 1);
            atomicAdd(&g_count[(int)b.x], 1);
            atomicAdd(&g_count[(int)b.y], 1);
        }
    } else {
        const int4* p = (const int4*)ids;
        for (int i = t; i < M4; i += stride) {
            int4 a = p[i];
            atomicAdd(&g_count[a.x], 1);
            atomicAdd(&g_count[a.y], 1);
            atomicAdd(&g_count[a.z], 1);
            atomicAdd(&g_count[a.w], 1);
        }
    }
    for (int i = M4 * 4 + t; i < M; i += stride)
        atomicAdd(&g_count[load_id(ids, i, is64)], 1);
}

// ----- 3-stage scan: partial sums -> scan of block sums -> final rescan -----
__global__ void scan_partial(int N) {
    __shared__ int wsum[32];
    int b = blockIdx.x, tid = threadIdx.x;
    int lane = tid & 31, warp = tid >> 5;
    int base = b * SCAN_TILE + tid * 4;
    int s = 0;
    #pragma unroll
    for (int k = 0; k < 4; k++) {
        int i = base + k;
        if (i < N) s += g_count[i];
    }
    #pragma unroll
    for (int o = 16; o > 0; o >>= 1) s += __shfl_down_sync(0xffffffffu, s, o);
    if (lane == 0) wsum[warp] = s;
    __syncthreads();
    if (warp == 0) {
        int w = wsum[lane];
        #pragma unroll
        for (int o = 16; o > 0; o >>= 1) w += __shfl_down_sync(0xffffffffu, w, o);
        if (lane == 0) g_bsum[b] = w;
    }
}

__global__ void scan_tops(int nb) {   // 1 block, nb <= 1024
    __shared__ int wsum[32];
    int tid = threadIdx.x, lane = tid & 31, warp = tid >> 5;
    int s = (tid < nb) ? g_bsum[tid] : 0;
    int x = s;
    #pragma unroll
    for (int o = 1; o < 32; o <<= 1) {
        int y = __shfl_up_sync(0xffffffffu, x, o);
        if (lane >= o) x += y;
    }
    if (lane == 31) wsum[warp] = x;
    __syncthreads();
    if (warp == 0) {
        int w = wsum[lane];
        #pragma unroll
        for (int o = 1; o < 32; o <<= 1) {
            int y = __shfl_up_sync(0xffffffffu, w, o);
            if (lane >= o) w += y;
        }
        wsum[lane] = w;
    }
    __syncthreads();
    if (tid < nb) g_boff[tid] = x - s + (warp > 0 ? wsum[warp - 1] : 0);
}

__global__ void scan_final(int N) {
    __shared__ int wsum[32];
    __shared__ int boff;
    int b = blockIdx.x, tid = threadIdx.x;
    int lane = tid & 31, warp = tid >> 5;
    if (tid == 0) boff = g_boff[b];
    int base = b * SCAN_TILE + tid * 4;
    int v[4]; int s = 0;
    #pragma unroll
    for (int k = 0; k < 4; k++) {
        int i = base + k;
        v[k] = (i < N) ? g_count[i] : 0;
        s += v[k];
    }
    int x = s;
    #pragma unroll
    for (int o = 1; o < 32; o <<= 1) {
        int y = __shfl_up_sync(0xffffffffu, x, o);
        if (lane >= o) x += y;
    }
    if (lane == 31) wsum[warp] = x;
    __syncthreads();
    if (warp == 0) {
        int w = wsum[lane];
        #pragma unroll
        for (int o = 1; o < 32; o <<= 1) {
            int y = __shfl_up_sync(0xffffffffu, w, o);
            if (lane >= o) w += y;
        }
        wsum[lane] = w;
    }
    __syncthreads();
    int run = x - s + (warp > 0 ? wsum[warp - 1] : 0) + boff;
    #pragma unroll
    for (int k = 0; k < 4; k++) {
        int i = base + k;
        if (i < N) {
            g_start[i]  = run;
            g_cursor[i] = run;
            run += v[k];
        }
    }
}

// Permutation: 4 independent atomic chains in flight per thread-iteration.
__global__ void build_perm_kernel(const void* __restrict__ ids, int M) {
    bool is64 = g_is64;
    int t = blockIdx.x * blockDim.x + threadIdx.x;
    int stride = gridDim.x * blockDim.x;
    int M4 = M >> 2;
    if (is64) {
        const longlong2* p = (const longlong2*)ids;
        for (int i = t; i < M4; i += stride) {
            longlong2 a = p[2 * i], b = p[2 * i + 1];
            int p0 = atomicAdd(&g_cursor[(int)a.x], 1);
            int p1 = atomicAdd(&g_cursor[(int)a.y], 1);
            int p2 = atomicAdd(&g_cursor[(int)b.x], 1);
            int p3 = atomicAdd(&g_cursor[(int)b.y], 1);
            int base = 4 * i;
            g_perm[p0] = base;
            g_perm[p1] = base + 1;
            g_perm[p2] = base + 2;
            g_perm[p3] = base + 3;
        }
    } else {
        const int4* p = (const int4*)ids;
        for (int i = t; i < M4; i += stride) {
            int4 a = p[i];
            int p0 = atomicAdd(&g_cursor[a.x], 1);
            int p1 = atomicAdd(&g_cursor[a.y], 1);
            int p2 = atomicAdd(&g_cursor[a.z], 1);
            int p3 = atomicAdd(&g_cursor[a.w], 1);
            int base = 4 * i;
            g_perm[p0] = base;
            g_perm[p1] = base + 1;
            g_perm[p2] = base + 2;
            g_perm[p3] = base + 3;
        }
    }
    for (int i = M4 * 4 + t; i < M; i += stride) {
        int id = load_id(ids, i, is64);
        g_perm[atomicAdd(&g_cursor[id], 1)] = i;
    }
}

// One warp per node; D == 128 (32 float4 per row, 1 per lane), 2-deep pipeline.
__global__ void gather_kernel(const float4* __restrict__ msgs4,
                              float* __restrict__ out, int N) {
    int gw   = (blockIdx.x * blockDim.x + threadIdx.x) >> 5;
    int lane = threadIdx.x & 31;
    if (gw >= N) return;

    int cnt   = g_count[gw];
    int start = g_start[gw];
    float4 acc = make_float4(0.f, 0.f, 0.f, 0.f);

    if (cnt > 0) {
        int idx  = g_perm[start];
        int idxn = (cnt > 1) ? g_perm[start + 1] : 0;
        float4 v = __ldg(&msgs4[(size_t)idx * 32 + lane]);
        for (int j = 1; j < cnt; j++) {
            int idxn2 = (j + 1 < cnt) ? g_perm[start + j + 1] : 0;
            float4 v2 = __ldg(&msgs4[(size_t)idxn * 32 + lane]);
            acc.x += v.x; acc.y += v.y; acc.z += v.z; acc.w += v.w;
            v = v2; idxn = idxn2;
        }
        acc.x += v.x; acc.y += v.y; acc.z += v.z; acc.w += v.w;
    }

    float inv = (cnt > 0) ? (1.0f / (float)cnt) : 0.0f;
    acc.x *= inv; acc.y *= inv; acc.z *= inv; acc.w *= inv;
    ((float4*)out)[(size_t)gw * 32 + lane] = acc;
}

// ---------- fallback path (generic D / oversized shapes) ----------
__device__ __forceinline__ void red_add_v4(float* addr, float4 v) {
    asm volatile("red.global.add.v4.f32 [%0], {%1, %2, %3, %4};"
                 :: "l"(addr), "f"(v.x), "f"(v.y), "f"(v.z), "f"(v.w) : "memory");
}
__device__ __forceinline__ void red_add_f32(float* addr, float v) {
    asm volatile("red.global.add.f32 [%0], %1;"
                 :: "l"(addr), "f"(v) : "memory");
}

__global__ void fb_init_kernel(float* __restrict__ sums, float* __restrict__ ids_out,
                               int N, int D, int has_ids) {
    long long total = (long long)N * D;
    for (long long i = blockIdx.x * (long long)blockDim.x + threadIdx.x;
         i < total; i += (long long)gridDim.x * blockDim.x)
        sums[i] = 0.f;
    for (long long i = blockIdx.x * (long long)blockDim.x + threadIdx.x;
         i < N; i += (long long)gridDim.x * blockDim.x) {
        if (i < MAX_NODES) g_fcounts[i] = 0.f;
        if (has_ids) ids_out[i] = (float)i;
    }
}

__global__ void fb_scatter_kernel(const void* __restrict__ ids,
                                  const float* __restrict__ msgs,
                                  float* __restrict__ sums, int M, int D) {
    int gwarp = (blockIdx.x * blockDim.x + threadIdx.x) >> 5;
    int lane  = threadIdx.x & 31;
    if (gwarp >= M) return;
    int id = load_id(ids, gwarp, g_is64 != 0);
    const float* row = msgs + (size_t)gwarp * D;
    float* dst = sums + (size_t)id * D;
    for (int c = lane * 4; c + 3 < D; c += 128)
        red_add_v4(dst + c, *(const float4*)(row + c));
    for (int c = (D / 4) * 4 + lane; c < D; c += 32)
        red_add_f32(dst + c, row[c]);
    if (lane == 0) red_add_f32(&g_fcounts[id], 1.0f);
}

__global__ void fb_normalize_kernel(float* __restrict__ sums, int N, int D) {
    long long total = (long long)N * D;
    for (long long i = blockIdx.x * (long long)blockDim.x + threadIdx.x;
         i < total; i += (long long)gridDim.x * blockDim.x) {
        int row = (int)(i / D);
        float inv = 1.0f / fmaxf(g_fcounts[row], 1.0f);
        sums[i] *= inv;
    }
}

extern "C" void kernel_launch(void* const* d_in, const int* in_sizes, int n_in,
                              void* d_out, int out_size) {
    const void*  ids  = d_in[0];
    const float* msgs = (const float*)d_in[1];

    int M = in_sizes[0];
    int D = in_sizes[1] / M;   // 128

    int N, has_ids;
    if (out_size % (D + 1) == 0) { N = out_size / (D + 1); has_ids = 1; }
    else                          { N = out_size / D;       has_ids = 0; }

    float* out     = (float*)d_out;
    float* ids_out = out;
    float* sums    = has_ids ? (out + N) : out;

    detect_kernel<<<1, 256>>>((const unsigned int*)ids, M);

    int nb = (N + SCAN_TILE - 1) / SCAN_TILE;
    bool fast = (D == 128) && (N <= MAX_NODES) && (M <= PERM_CAP) && (nb <= 1024);

    if (fast) {
        {
            int blocks = (N + 255) / 256; if (blocks > 2048) blocks = 2048;
            init_kernel<<<blocks, 256>>>(ids_out, N, has_ids);
        }
        {
            int blocks = (M / 4 + 255) / 256; if (blocks > 2048) blocks = 2048;
            if (blocks < 1) blocks = 1;
            hist_kernel<<<blocks, 256>>>(ids, M);
        }
        scan_partial<<<nb, 1024>>>(N);
        scan_tops<<<1, 1024>>>(nb);
        scan_final<<<nb, 1024>>>(N);
        {
            int blocks = (M / 4 + 255) / 256; if (blocks > 2048) blocks = 2048;
            if (blocks < 1) blocks = 1;
            build_perm_kernel<<<blocks, 256>>>(ids, M);
        }
        {
            long long threads = (long long)N * 32;
            int blocks = (int)((threads + 255) / 256);
            gather_kernel<<<blocks, 256>>>((const float4*)msgs, sums, N);
        }
    } else {
        {
            long long total = (long long)N * D;
            int blocks = (int)((total + 255) / 256); if (blocks > 4096) blocks = 4096;
            fb_init_kernel<<<blocks, 256>>>(sums, ids_out, N, D, has_ids);
        }
        {
            long long threads = (long long)M * 32;
            int blocks = (int)((threads + 255) / 256);
            fb_scatter_kernel<<<blocks, 256>>>(ids, msgs, sums, M, D);
        }
        {
            long long total = (long long)N * D;
            int blocks = (int)((total + 255) / 256); if (blocks > 4096) blocks = 4096;
            fb_normalize_kernel<<<blocks, 256>>>(sums, N, D);
        }
    }
}